// round 8
// baseline (speedup 1.0000x reference)
#include <cuda_runtime.h>
#include <math.h>
#include <float.h>

#define L_    2
#define B_    32
#define S_    512
#define D_    512
#define H_    8
#define DH_   64
#define DFF_  2048
#define KIDX_ 5
#define M_    (B_*S_)   // 16384 rows

// ---------------- scratch (device globals; no runtime allocation) ----------------
__device__ float g_x[B_*S_*D_];
__device__ float g_y[B_*S_*D_];
__device__ float g_qk[B_*S_*D_];
__device__ float g_v[B_*S_*D_];
__device__ float g_attn[B_*S_*D_];
__device__ float g_tmp[B_*S_*D_];
__device__ float g_ff[(size_t)B_*S_*DFF_];

// ---------------- x = q_emb + pos ; y = i_emb + pos ----------------
__global__ void add_pos_kernel(const float* __restrict__ q,
                               const float* __restrict__ ie,
                               const float* __restrict__ pos) {
    int idx = blockIdx.x * blockDim.x + threadIdx.x;   // over B*S*D
    int sd  = idx % (S_ * D_);
    float p = pos[sd];
    g_x[idx] = q[idx]  + p;
    g_y[idx] = ie[idx] + p;
}

// ---------------- tf32 helpers ----------------
__device__ __forceinline__ float f2tf32(float x) {
    unsigned y;
    asm("cvt.rna.tf32.f32 %0, %1;" : "=r"(y) : "f"(x));
    return __uint_as_float(y);
}

__device__ __forceinline__ void mma_tf32(float* c, const unsigned* a, const unsigned* b) {
    asm volatile("mma.sync.aligned.m16n8k8.row.col.f32.tf32.tf32.f32 "
                 "{%0,%1,%2,%3}, {%4,%5,%6,%7}, {%8,%9}, {%0,%1,%2,%3};\n"
                 : "+f"(c[0]), "+f"(c[1]), "+f"(c[2]), "+f"(c[3])
                 : "r"(a[0]), "r"(a[1]), "r"(a[2]), "r"(a[3]),
                   "r"(b[0]), "r"(b[1]));
}

// ---------------- C[M,N] = A[M,K] @ W[K,N] + bias (optional ReLU) ------------
// 3xTF32 tensor-core GEMM: 128x128 tile, BK=16, 8 warps (2x4), warp tile 64x32.
// Each operand split x = hi + lo (tf32 each); product = lo*hi + hi*lo + hi*hi.
#define BM_ 128
#define BN_ 128
#define BK_ 16

__global__ __launch_bounds__(256)
void gemm_tc_kernel(const float* __restrict__ A, const float* __restrict__ W,
                    const float* __restrict__ bias, float* __restrict__ C,
                    int K, int N, int relu) {
    __shared__ float As_h[BK_][BM_ + 4];   // [k][m] hi
    __shared__ float As_l[BK_][BM_ + 4];   // [k][m] lo
    __shared__ float Ws_h[BK_][BN_ + 4];   // [k][n] hi
    __shared__ float Ws_l[BK_][BN_ + 4];   // [k][n] lo

    int tid  = threadIdx.x;
    int lane = tid & 31, wid = tid >> 5;
    int qa   = lane & 3, ra = lane >> 2;         // quad col / group row
    int warp_m = (wid >> 2) * 64;                // 2 warps along M
    int warp_n = (wid & 3) * 32;                 // 4 warps along N
    int bm = blockIdx.y * BM_, bn = blockIdx.x * BN_;

    float acc[4][4][4];
    #pragma unroll
    for (int mt = 0; mt < 4; mt++)
        #pragma unroll
        for (int nt = 0; nt < 4; nt++)
            #pragma unroll
            for (int r = 0; r < 4; r++) acc[mt][nt][r] = 0.f;

    float4 rA[2], rW[2];

    // prefetch k0 = 0
    #pragma unroll
    for (int e = 0; e < 2; e++) {
        int idx = tid + e * 256;
        int row = idx >> 2, c4 = idx & 3;                       // A: 128 rows x 4 f4
        rA[e] = *(const float4*)&A[(size_t)(bm + row) * K + c4 * 4];
        int rw = idx >> 5, cw = idx & 31;                       // W: 16 rows x 32 f4
        rW[e] = *(const float4*)&W[(size_t)rw * N + bn + cw * 4];
    }

    for (int k0 = 0; k0 < K; k0 += BK_) {
        // store current tile with hi/lo tf32 split
        #pragma unroll
        for (int e = 0; e < 2; e++) {
            int idx = tid + e * 256;
            int row = idx >> 2, c4 = idx & 3;
            float av[4] = {rA[e].x, rA[e].y, rA[e].z, rA[e].w};
            #pragma unroll
            for (int u = 0; u < 4; u++) {
                float hi = f2tf32(av[u]);
                As_h[c4 * 4 + u][row] = hi;
                As_l[c4 * 4 + u][row] = f2tf32(av[u] - hi);
            }
            int rw = idx >> 5, cw = idx & 31;
            float wv[4] = {rW[e].x, rW[e].y, rW[e].z, rW[e].w};
            float4 th, tl;
            th.x = f2tf32(wv[0]); tl.x = f2tf32(wv[0] - th.x);
            th.y = f2tf32(wv[1]); tl.y = f2tf32(wv[1] - th.y);
            th.z = f2tf32(wv[2]); tl.z = f2tf32(wv[2] - th.z);
            th.w = f2tf32(wv[3]); tl.w = f2tf32(wv[3] - th.w);
            *(float4*)&Ws_h[rw][cw * 4] = th;
            *(float4*)&Ws_l[rw][cw * 4] = tl;
        }
        __syncthreads();

        // prefetch next tile
        if (k0 + BK_ < K) {
            int kn = k0 + BK_;
            #pragma unroll
            for (int e = 0; e < 2; e++) {
                int idx = tid + e * 256;
                int row = idx >> 2, c4 = idx & 3;
                rA[e] = *(const float4*)&A[(size_t)(bm + row) * K + kn + c4 * 4];
                int rw = idx >> 5, cw = idx & 31;
                rW[e] = *(const float4*)&W[(size_t)(kn + rw) * N + bn + cw * 4];
            }
        }

        // compute: two k8 steps, 3 MMAs (lo*hi, hi*lo, hi*hi) per microtile
        #pragma unroll
        for (int kk = 0; kk < BK_; kk += 8) {
            unsigned bh[4][2], bl[4][2];
            #pragma unroll
            for (int nt = 0; nt < 4; nt++) {
                int nb = warp_n + nt * 8;
                bh[nt][0] = __float_as_uint(Ws_h[kk + qa][nb + ra]);
                bh[nt][1] = __float_as_uint(Ws_h[kk + 4 + qa][nb + ra]);
                bl[nt][0] = __float_as_uint(Ws_l[kk + qa][nb + ra]);
                bl[nt][1] = __float_as_uint(Ws_l[kk + 4 + qa][nb + ra]);
            }
            #pragma unroll
            for (int mt = 0; mt < 4; mt++) {
                int rm = warp_m + mt * 16;
                unsigned ah[4], al[4];
                ah[0] = __float_as_uint(As_h[kk + qa][rm + ra]);
                ah[1] = __float_as_uint(As_h[kk + qa][rm + ra + 8]);
                ah[2] = __float_as_uint(As_h[kk + 4 + qa][rm + ra]);
                ah[3] = __float_as_uint(As_h[kk + 4 + qa][rm + ra + 8]);
                al[0] = __float_as_uint(As_l[kk + qa][rm + ra]);
                al[1] = __float_as_uint(As_l[kk + qa][rm + ra + 8]);
                al[2] = __float_as_uint(As_l[kk + 4 + qa][rm + ra]);
                al[3] = __float_as_uint(As_l[kk + 4 + qa][rm + ra + 8]);
                #pragma unroll
                for (int nt = 0; nt < 4; nt++) {
                    mma_tf32(acc[mt][nt], al, bh[nt]);   // lo*hi
                    mma_tf32(acc[mt][nt], ah, bl[nt]);   // hi*lo
                    mma_tf32(acc[mt][nt], ah, bh[nt]);   // hi*hi
                }
            }
        }
        __syncthreads();
    }

    // epilogue
    #pragma unroll
    for (int mt = 0; mt < 4; mt++) {
        #pragma unroll
        for (int nt = 0; nt < 4; nt++) {
            int row = bm + warp_m + mt * 16 + ra;
            int col = bn + warp_n + nt * 8 + 2 * qa;
            float2 bb = *(const float2*)&bias[col];
            float o0 = acc[mt][nt][0] + bb.x;
            float o1 = acc[mt][nt][1] + bb.y;
            float o2 = acc[mt][nt][2] + bb.x;
            float o3 = acc[mt][nt][3] + bb.y;
            if (relu) {
                o0 = fmaxf(o0, 0.f); o1 = fmaxf(o1, 0.f);
                o2 = fmaxf(o2, 0.f); o3 = fmaxf(o3, 0.f);
            }
            float2 v0 = make_float2(o0, o1);
            float2 v1 = make_float2(o2, o3);
            *(float2*)&C[(size_t)row * N + col]       = v0;
            *(float2*)&C[(size_t)(row + 8) * N + col] = v1;
        }
    }
}

// ---------------- sparse causal attention ----------------
// One warp per query row i; 8 consecutive rows of the same (b,h) per block so
// K/V tiles are loaded to SMEM once per block. Vectorized LDS (float4) on QK,
// shuffle-broadcast probs on PV.
__global__ __launch_bounds__(256)
void attn_kernel(const float* __restrict__ qk, const float* __restrict__ v,
                 float* __restrict__ out) {
    __shared__ float tile[32][68];    // K tile, then reused as V tile (16B-aligned rows)
    __shared__ float probs[8][S_];
    __shared__ float qs[8][64];

    int w = threadIdx.y, lane = threadIdx.x;
    int blk = blockIdx.x;
    int bh  = blk >> 6;              // S/8 = 64 blocks per (b,h)
    int i0  = (blk & 63) * 8;
    int b = bh >> 3, h = bh & 7;
    int i = i0 + w;                  // this warp's query row
    int tid = w * 32 + lane;

    size_t qoff = ((size_t)(b * S_ + i) * D_ + h * DH_);
    qs[w][lane]      = qk[qoff + lane];
    qs[w][lane + 32] = qk[qoff + lane + 32];

    int nkeys  = i0 + 7;             // max keys needed by any warp in block
    int ntiles = (nkeys + 31) >> 5;
    __syncthreads();

    // ---- phase 1: scores (q . k_j / 8) ----
    for (int t = 0; t < ntiles; t++) {
        int j0 = t << 5;
        #pragma unroll
        for (int e = 0; e < 2; e++) {
            int li = tid + e * 256;          // 512 float4
            int jr = li >> 4, d4 = li & 15;
            *(float4*)&tile[jr][d4 * 4] =
                *(const float4*)&qk[((size_t)(b * S_ + j0 + jr) * D_ + h * DH_) + d4 * 4];
        }
        __syncthreads();
        int j = j0 + lane;
        if (j < i) {
            const float4* tv = (const float4*)&tile[lane][0];
            const float4* qv = (const float4*)&qs[w][0];
            float s = 0.f;
            #pragma unroll
            for (int d4 = 0; d4 < 16; d4++) {
                float4 a = tv[d4], q4 = qv[d4];
                s += a.x * q4.x + a.y * q4.y + a.z * q4.z + a.w * q4.w;
            }
            probs[w][j] = s * 0.125f;
        }
        __syncthreads();
    }

    // ---- phase 2: softmax; phase 3: top-k re-softmax (warp-local) ----
    if (i > 0) {
        float mx = -FLT_MAX;
        for (int j = lane; j < i; j += 32) mx = fmaxf(mx, probs[w][j]);
        for (int o = 16; o; o >>= 1) mx = fmaxf(mx, __shfl_xor_sync(~0u, mx, o));
        float sum = 0.f;
        for (int j = lane; j < i; j += 32) {
            float e = expf(probs[w][j] - mx);
            probs[w][j] = e; sum += e;
        }
        for (int o = 16; o; o >>= 1) sum += __shfl_xor_sync(~0u, sum, o);
        float inv = 1.f / sum;
        for (int j = lane; j < i; j += 32) probs[w][j] *= inv;

        if (i > KIDX_) {
            // find 5th-largest prob (counting multiplicity): iterative max extraction
            float cur = FLT_MAX;
            int kept = 0;
            float m1 = -FLT_MAX;   // top-1 prob (for re-softmax stability)
            for (int it = 0; it < KIDX_ && kept < KIDX_; it++) {
                float lm = -FLT_MAX;
                for (int j = lane; j < i; j += 32) {
                    float p = probs[w][j];
                    if (p < cur && p > lm) lm = p;
                }
                for (int o = 16; o; o >>= 1) lm = fmaxf(lm, __shfl_xor_sync(~0u, lm, o));
                int lc = 0;
                for (int j = lane; j < i; j += 32) if (probs[w][j] == lm) lc++;
                for (int o = 16; o; o >>= 1) lc += __shfl_xor_sync(~0u, lc, o);
                if (it == 0) m1 = lm;
                kept += lc;
                cur = lm;
            }
            float thresh = cur;
            // re-softmax OF THE PROBABILITIES over the kept set
            float sum2 = 0.f;
            for (int j = lane; j < i; j += 32) {
                float p = probs[w][j];
                float wt = (p >= thresh) ? expf(p - m1) : 0.f;
                probs[w][j] = wt; sum2 += wt;
            }
            for (int o = 16; o; o >>= 1) sum2 += __shfl_xor_sync(~0u, sum2, o);
            float inv2 = 1.f / sum2;
            for (int j = lane; j < i; j += 32) probs[w][j] *= inv2;
        }
    }

    // ---- phase 4: out = probs @ V (V tiled through SMEM, shuffle-broadcast wt) ----
    float acc0 = 0.f, acc1 = 0.f;
    for (int t = 0; t < ntiles; t++) {
        int j0 = t << 5;
        __syncthreads();      // previous tile use complete before overwrite
        #pragma unroll
        for (int e = 0; e < 2; e++) {
            int li = tid + e * 256;
            int jr = li >> 4, d4 = li & 15;
            *(float4*)&tile[jr][d4 * 4] =
                *(const float4*)&v[((size_t)(b * S_ + j0 + jr) * D_ + h * DH_) + d4 * 4];
        }
        __syncthreads();
        int jend = i - j0; if (jend > 32) jend = 32;
        float pv = probs[w][j0 + lane];
        for (int jj = 0; jj < jend; jj++) {
            float wt = __shfl_sync(~0u, pv, jj);
            acc0 += wt * tile[jj][lane];
            acc1 += wt * tile[jj][lane + 32];
        }
    }
    size_t ooff = ((size_t)(b * S_ + i) * D_ + h * DH_);
    out[ooff + lane]      = (i == 0) ? 0.f : acc0;   // zero_pad row 0
    out[ooff + lane + 32] = (i == 0) ? 0.f : acc1;
}

// ---------------- out = LayerNorm(xin + delta) * g + b ----------------
__global__ __launch_bounds__(128)
void resid_ln_kernel(const float* __restrict__ xin, const float* __restrict__ delta,
                     const float* __restrict__ g, const float* __restrict__ bta,
                     float* __restrict__ out) {
    __shared__ float red[4];
    int row = blockIdx.x;
    int t = threadIdx.x;            // 128 threads, 4 elems each
    float v[4];
    float s = 0.f;
    #pragma unroll
    for (int e = 0; e < 4; e++) {
        int d = t + e * 128;
        v[e] = xin[(size_t)row * D_ + d] + delta[(size_t)row * D_ + d];
        s += v[e];
    }
    for (int o = 16; o; o >>= 1) s += __shfl_xor_sync(~0u, s, o);
    if ((t & 31) == 0) red[t >> 5] = s;
    __syncthreads();
    s = red[0] + red[1] + red[2] + red[3];
    float mean = s * (1.f / D_);

    float sq = 0.f;
    #pragma unroll
    for (int e = 0; e < 4; e++) { float dd = v[e] - mean; sq += dd * dd; }
    __syncthreads();                // red reuse
    for (int o = 16; o; o >>= 1) sq += __shfl_xor_sync(~0u, sq, o);
    if ((t & 31) == 0) red[t >> 5] = sq;
    __syncthreads();
    sq = red[0] + red[1] + red[2] + red[3];
    float rstd = rsqrtf(sq * (1.f / D_) + 1e-5f);

    #pragma unroll
    for (int e = 0; e < 4; e++) {
        int d = t + e * 128;
        out[(size_t)row * D_ + d] = (v[e] - mean) * rstd * g[d] + bta[d];
    }
}

// ---------------- launcher ----------------
extern "C" void kernel_launch(void* const* d_in, const int* in_sizes, int n_in,
                              void* d_out, int out_size) {
    const float* question = (const float*)d_in[0];
    const float* inter    = (const float*)d_in[1];
    const float* pos      = (const float*)d_in[2];
    const float* Wk  = (const float*)d_in[3];
    const float* bk  = (const float*)d_in[4];
    const float* Wv  = (const float*)d_in[5];
    const float* bv  = (const float*)d_in[6];
    const float* Wo  = (const float*)d_in[7];
    const float* bo  = (const float*)d_in[8];
    const float* ln1g = (const float*)d_in[9];
    const float* ln1b = (const float*)d_in[10];
    const float* W1  = (const float*)d_in[11];
    const float* b1  = (const float*)d_in[12];
    const float* W2  = (const float*)d_in[13];
    const float* b2  = (const float*)d_in[14];
    const float* ln2g = (const float*)d_in[15];
    const float* ln2b = (const float*)d_in[16];

    float *x, *y, *qkb, *vb, *attnb, *tmpb, *ffb;
    cudaGetSymbolAddress((void**)&x,     g_x);
    cudaGetSymbolAddress((void**)&y,     g_y);
    cudaGetSymbolAddress((void**)&qkb,   g_qk);
    cudaGetSymbolAddress((void**)&vb,    g_v);
    cudaGetSymbolAddress((void**)&attnb, g_attn);
    cudaGetSymbolAddress((void**)&tmpb,  g_tmp);
    cudaGetSymbolAddress((void**)&ffb,   g_ff);

    add_pos_kernel<<<(B_ * S_ * D_) / 256, 256>>>(question, inter, pos);

    for (int l = 0; l < L_; l++) {
        const float* Wkl = Wk + (size_t)l * D_ * D_;
        const float* Wvl = Wv + (size_t)l * D_ * D_;
        const float* Wol = Wo + (size_t)l * D_ * D_;
        const float* W1l = W1 + (size_t)l * D_ * DFF_;
        const float* W2l = W2 + (size_t)l * DFF_ * D_;

        dim3 gD(D_ / BN_, M_ / BM_);       // N=512 output
        dim3 gF(DFF_ / BN_, M_ / BM_);     // N=2048 output

        gemm_tc_kernel<<<gD, 256>>>(x, Wkl, bk + l * D_, qkb, D_, D_, 0);
        gemm_tc_kernel<<<gD, 256>>>(y, Wvl, bv + l * D_, vb,  D_, D_, 0);
        attn_kernel<<<B_ * H_ * (S_ / 8), dim3(32, 8)>>>(qkb, vb, attnb);
        gemm_tc_kernel<<<gD, 256>>>(attnb, Wol, bo + l * D_, tmpb, D_, D_, 0);
        resid_ln_kernel<<<M_, 128>>>(x, tmpb, ln1g + l * D_, ln1b + l * D_, x);
        gemm_tc_kernel<<<gF, 256>>>(x, W1l, b1 + l * DFF_, ffb, D_, DFF_, 1);
        gemm_tc_kernel<<<gD, 256>>>(ffb, W2l, b2 + l * D_, tmpb, DFF_, D_, 0);
        float* lnout = (l == L_ - 1) ? (float*)d_out : x;
        resid_ln_kernel<<<M_, 128>>>(x, tmpb, ln2g + l * D_, ln2b + l * D_, lnout);
    }
}

// round 12
// speedup vs baseline: 1.8832x; 1.8832x over previous
#include <cuda_runtime.h>
#include <cuda_fp16.h>
#include <math.h>
#include <float.h>
#include <stdint.h>

#define L_    2
#define B_    32
#define S_    512
#define D_    512
#define H_    8
#define DH_   64
#define DFF_  2048
#define KIDX_ 5
#define M_    (B_*S_)   // 16384 rows

// ---------------- scratch (device globals; no runtime allocation) ----------------
__device__ float g_x[B_*S_*D_];
__device__ float g_y[B_*S_*D_];
__device__ float g_qk[B_*S_*D_];
__device__ float g_v[B_*S_*D_];
__device__ float g_attn[B_*S_*D_];
__device__ float g_tmp[B_*S_*D_];
__device__ float g_ff[(size_t)B_*S_*DFF_];

// ---------------- x = q_emb + pos ; y = i_emb + pos ----------------
__global__ void add_pos_kernel(const float* __restrict__ q,
                               const float* __restrict__ ie,
                               const float* __restrict__ pos) {
    int idx = blockIdx.x * blockDim.x + threadIdx.x;   // over B*S*D
    int sd  = idx % (S_ * D_);
    float p = pos[sd];
    g_x[idx] = q[idx]  + p;
    g_y[idx] = ie[idx] + p;
}

// ---------------- fp16 MMA helper ----------------
__device__ __forceinline__ void mma_f16(float* c, const unsigned* a, const unsigned* b) {
    asm volatile("mma.sync.aligned.m16n8k16.row.col.f32.f16.f16.f32 "
                 "{%0,%1,%2,%3}, {%4,%5,%6,%7}, {%8,%9}, {%0,%1,%2,%3};\n"
                 : "+f"(c[0]), "+f"(c[1]), "+f"(c[2]), "+f"(c[3])
                 : "r"(a[0]), "r"(a[1]), "r"(a[2]), "r"(a[3]),
                   "r"(b[0]), "r"(b[1]));
}

// split x = hi + lo (both fp16)
__device__ __forceinline__ void split2(float x, float y, __half2& h, __half2& l) {
    __half hx = __float2half_rn(x);
    __half hy = __float2half_rn(y);
    __half lx = __float2half_rn(x - __half2float(hx));
    __half ly = __float2half_rn(y - __half2float(hy));
    h = __halves2half2(hx, hy);
    l = __halves2half2(lx, ly);
}

// ---------------- 3xFP16 tensor-core GEMM ----------------
// C[M,N] = A[M,K] @ W[K,N] + bias (optional ReLU).
// CTA tile 128x128, BK=32, 8 warps (2x4), warp tile 64x32.
// SMEM stores k-adjacent half2 pairs: Ah/Al[k2][m], Bh/Bl[k2][n] (k2 = k/2).
// Double-buffered with register prefetch of next global tile.
#define BK_  32
#define NK2_ 16                 // BK/2
#define PADW 132                // row width in half2 (528B, 16B-aligned rows)
#define ARR_ (NK2_*PADW)        // 2112 half2 per array
#define BUFH (4*ARR_)           // Ah, Al, Bh, Bl
#define GSMEM_BYTES (2*BUFH*4)  // 67584 bytes

__global__ __launch_bounds__(256)
void gemm_f16x3(const float* __restrict__ A, const float* __restrict__ W,
                const float* __restrict__ bias, float* __restrict__ C,
                int K, int N, int relu) {
    extern __shared__ __align__(16) char smraw[];
    __half2* sm = (__half2*)smraw;

    int tid  = threadIdx.x;
    int lane = tid & 31, wid = tid >> 5;
    int qa   = lane & 3, g = lane >> 2;           // quad / group-row
    int warp_m = (wid >> 2) * 64;                 // 2 warps along M
    int warp_n = (wid & 3) * 32;                  // 4 warps along N
    int bm = blockIdx.y * 128, bn = blockIdx.x * 128;

    float acc[4][4][4];
    #pragma unroll
    for (int mt = 0; mt < 4; mt++)
        #pragma unroll
        for (int nt = 0; nt < 4; nt++)
            #pragma unroll
            for (int r = 0; r < 4; r++) acc[mt][nt][r] = 0.f;

    // per-thread load assignments
    // A: 4 items: idx = tid + e*256; m = idx & 127; k4 = idx >> 7 (0..7) -> k = 4*k4
    // W: 2 items: idx = tid + e*256; k2 = idx >> 5 (0..15); n4 = idx & 31 -> n = 4*n4
    float4 rA[4], rW0[2], rW1[2];

    // prefetch tile 0
    #pragma unroll
    for (int e = 0; e < 4; e++) {
        int idx = tid + e * 256;
        int m = idx & 127, k4 = idx >> 7;
        rA[e] = *(const float4*)&A[(size_t)(bm + m) * K + k4 * 4];
    }
    #pragma unroll
    for (int e = 0; e < 2; e++) {
        int idx = tid + e * 256;
        int k2 = idx >> 5, n4 = idx & 31;
        rW0[e] = *(const float4*)&W[(size_t)(2 * k2)     * N + bn + n4 * 4];
        rW1[e] = *(const float4*)&W[(size_t)(2 * k2 + 1) * N + bn + n4 * 4];
    }

    int NT = K / BK_;
    for (int kt = 0; kt < NT; kt++) {
        __half2* Ah = sm + (kt & 1) * BUFH;
        __half2* Al = Ah + ARR_;
        __half2* Bh = Al + ARR_;
        __half2* Bl = Bh + ARR_;

        // ---- store prefetched tile to SMEM with hi/lo fp16 split ----
        #pragma unroll
        for (int e = 0; e < 4; e++) {
            int idx = tid + e * 256;
            int m = idx & 127, k4 = idx >> 7;
            __half2 h0, l0, h1, l1;
            split2(rA[e].x, rA[e].y, h0, l0);
            split2(rA[e].z, rA[e].w, h1, l1);
            Ah[(2 * k4)     * PADW + m] = h0;
            Ah[(2 * k4 + 1) * PADW + m] = h1;
            Al[(2 * k4)     * PADW + m] = l0;
            Al[(2 * k4 + 1) * PADW + m] = l1;
        }
        #pragma unroll
        for (int e = 0; e < 2; e++) {
            int idx = tid + e * 256;
            int k2 = idx >> 5, n4 = idx & 31;
            const float* p0 = (const float*)&rW0[e];
            const float* p1 = (const float*)&rW1[e];
            __half2 hh[4], ll[4];
            #pragma unroll
            for (int j = 0; j < 4; j++) {
                __half h0 = __float2half_rn(p0[j]);
                __half h1 = __float2half_rn(p1[j]);
                __half l0 = __float2half_rn(p0[j] - __half2float(h0));
                __half l1 = __float2half_rn(p1[j] - __half2float(h1));
                hh[j] = __halves2half2(h0, h1);   // (k even, k odd) pair
                ll[j] = __halves2half2(l0, l1);
            }
            *(uint4*)&Bh[k2 * PADW + n4 * 4] = *(uint4*)hh;
            *(uint4*)&Bl[k2 * PADW + n4 * 4] = *(uint4*)ll;
        }
        __syncthreads();

        // ---- prefetch next tile into registers ----
        if (kt + 1 < NT) {
            int k0n = (kt + 1) * BK_;
            #pragma unroll
            for (int e = 0; e < 4; e++) {
                int idx = tid + e * 256;
                int m = idx & 127, k4 = idx >> 7;
                rA[e] = *(const float4*)&A[(size_t)(bm + m) * K + k0n + k4 * 4];
            }
            #pragma unroll
            for (int e = 0; e < 2; e++) {
                int idx = tid + e * 256;
                int k2 = idx >> 5, n4 = idx & 31;
                rW0[e] = *(const float4*)&W[(size_t)(k0n + 2 * k2)     * N + bn + n4 * 4];
                rW1[e] = *(const float4*)&W[(size_t)(k0n + 2 * k2 + 1) * N + bn + n4 * 4];
            }
        }

        // ---- compute: two k16 steps ----
        #pragma unroll
        for (int s = 0; s < 2; s++) {
            int s8 = s * 8;
            unsigned bh[4][2], bl[4][2];
            #pragma unroll
            for (int nt = 0; nt < 4; nt++) {
                int nb = warp_n + nt * 8 + g;
                bh[nt][0] = *(const unsigned*)&Bh[(s8 + qa)     * PADW + nb];
                bh[nt][1] = *(const unsigned*)&Bh[(s8 + qa + 4) * PADW + nb];
                bl[nt][0] = *(const unsigned*)&Bl[(s8 + qa)     * PADW + nb];
                bl[nt][1] = *(const unsigned*)&Bl[(s8 + qa + 4) * PADW + nb];
            }
            #pragma unroll
            for (int mt = 0; mt < 4; mt++) {
                int rm = warp_m + mt * 16 + g;
                unsigned ah[4], al[4];
                ah[0] = *(const unsigned*)&Ah[(s8 + qa)     * PADW + rm];
                ah[1] = *(const unsigned*)&Ah[(s8 + qa)     * PADW + rm + 8];
                ah[2] = *(const unsigned*)&Ah[(s8 + qa + 4) * PADW + rm];
                ah[3] = *(const unsigned*)&Ah[(s8 + qa + 4) * PADW + rm + 8];
                al[0] = *(const unsigned*)&Al[(s8 + qa)     * PADW + rm];
                al[1] = *(const unsigned*)&Al[(s8 + qa)     * PADW + rm + 8];
                al[2] = *(const unsigned*)&Al[(s8 + qa + 4) * PADW + rm];
                al[3] = *(const unsigned*)&Al[(s8 + qa + 4) * PADW + rm + 8];
                #pragma unroll
                for (int nt = 0; nt < 4; nt++) {
                    mma_f16(acc[mt][nt], al, bh[nt]);   // lo*hi
                    mma_f16(acc[mt][nt], ah, bl[nt]);   // hi*lo
                    mma_f16(acc[mt][nt], ah, bh[nt]);   // hi*hi
                }
            }
        }
        __syncthreads();
    }

    // ---- epilogue (C frag: c0=C[g][2qa], c1=C[g][2qa+1], c2/c3 at row g+8) ----
    #pragma unroll
    for (int mt = 0; mt < 4; mt++) {
        #pragma unroll
        for (int nt = 0; nt < 4; nt++) {
            int row = bm + warp_m + mt * 16 + g;
            int col = bn + warp_n + nt * 8 + 2 * qa;
            float2 bb = *(const float2*)&bias[col];
            float o0 = acc[mt][nt][0] + bb.x;
            float o1 = acc[mt][nt][1] + bb.y;
            float o2 = acc[mt][nt][2] + bb.x;
            float o3 = acc[mt][nt][3] + bb.y;
            if (relu) {
                o0 = fmaxf(o0, 0.f); o1 = fmaxf(o1, 0.f);
                o2 = fmaxf(o2, 0.f); o3 = fmaxf(o3, 0.f);
            }
            *(float2*)&C[(size_t)row * N + col]       = make_float2(o0, o1);
            *(float2*)&C[(size_t)(row + 8) * N + col] = make_float2(o2, o3);
        }
    }
}

// ---------------- sparse causal attention ----------------
// One warp per query row i; 8 consecutive rows per block share K/V tiles.
// float4 LDS on QK; float2 accumulation + shuffle-broadcast probs on PV.
__global__ __launch_bounds__(256)
void attn_kernel(const float* __restrict__ qk, const float* __restrict__ v,
                 float* __restrict__ out) {
    __shared__ float tile[32][68];
    __shared__ float probs[8][S_];
    __shared__ float qs[8][64];

    int w = threadIdx.y, lane = threadIdx.x;
    int blk = blockIdx.x;
    int bh  = blk >> 6;
    int i0  = (blk & 63) * 8;
    int b = bh >> 3, h = bh & 7;
    int i = i0 + w;
    int tid = w * 32 + lane;

    size_t qoff = ((size_t)(b * S_ + i) * D_ + h * DH_);
    qs[w][lane]      = qk[qoff + lane];
    qs[w][lane + 32] = qk[qoff + lane + 32];

    int nkeys  = i0 + 7;
    int ntiles = (nkeys + 31) >> 5;
    __syncthreads();

    // ---- phase 1: scores ----
    for (int t = 0; t < ntiles; t++) {
        int j0 = t << 5;
        #pragma unroll
        for (int e = 0; e < 2; e++) {
            int li = tid + e * 256;
            int jr = li >> 4, d4 = li & 15;
            *(float4*)&tile[jr][d4 * 4] =
                *(const float4*)&qk[((size_t)(b * S_ + j0 + jr) * D_ + h * DH_) + d4 * 4];
        }
        __syncthreads();
        int j = j0 + lane;
        if (j < i) {
            const float4* tv = (const float4*)&tile[lane][0];
            const float4* qv = (const float4*)&qs[w][0];
            float s = 0.f;
            #pragma unroll
            for (int d4 = 0; d4 < 16; d4++) {
                float4 a = tv[d4], q4 = qv[d4];
                s += a.x * q4.x + a.y * q4.y + a.z * q4.z + a.w * q4.w;
            }
            probs[w][j] = s * 0.125f;
        }
        __syncthreads();
    }

    // ---- phase 2+3: softmax, top-k re-softmax ----
    if (i > 0) {
        float mx = -FLT_MAX;
        for (int j = lane; j < i; j += 32) mx = fmaxf(mx, probs[w][j]);
        for (int o = 16; o; o >>= 1) mx = fmaxf(mx, __shfl_xor_sync(~0u, mx, o));
        float sum = 0.f;
        for (int j = lane; j < i; j += 32) {
            float e = expf(probs[w][j] - mx);
            probs[w][j] = e; sum += e;
        }
        for (int o = 16; o; o >>= 1) sum += __shfl_xor_sync(~0u, sum, o);
        float inv = 1.f / sum;
        for (int j = lane; j < i; j += 32) probs[w][j] *= inv;

        if (i > KIDX_) {
            float cur = FLT_MAX;
            int kept = 0;
            float m1 = -FLT_MAX;
            for (int it = 0; it < KIDX_ && kept < KIDX_; it++) {
                float lm = -FLT_MAX;
                for (int j = lane; j < i; j += 32) {
                    float p = probs[w][j];
                    if (p < cur && p > lm) lm = p;
                }
                for (int o = 16; o; o >>= 1) lm = fmaxf(lm, __shfl_xor_sync(~0u, lm, o));
                int lc = 0;
                for (int j = lane; j < i; j += 32) if (probs[w][j] == lm) lc++;
                for (int o = 16; o; o >>= 1) lc += __shfl_xor_sync(~0u, lc, o);
                if (it == 0) m1 = lm;
                kept += lc;
                cur = lm;
            }
            float thresh = cur;
            float sum2 = 0.f;
            for (int j = lane; j < i; j += 32) {
                float p = probs[w][j];
                float wt = (p >= thresh) ? expf(p - m1) : 0.f;
                probs[w][j] = wt; sum2 += wt;
            }
            for (int o = 16; o; o >>= 1) sum2 += __shfl_xor_sync(~0u, sum2, o);
            float inv2 = 1.f / sum2;
            for (int j = lane; j < i; j += 32) probs[w][j] *= inv2;
        }
    }

    // ---- phase 4: out = probs @ V (float2 accumulation: lane owns d = 2*lane, 2*lane+1) ----
    float2 acc = make_float2(0.f, 0.f);
    for (int t = 0; t < ntiles; t++) {
        int j0 = t << 5;
        __syncthreads();
        #pragma unroll
        for (int e = 0; e < 2; e++) {
            int li = tid + e * 256;
            int jr = li >> 4, d4 = li & 15;
            *(float4*)&tile[jr][d4 * 4] =
                *(const float4*)&v[((size_t)(b * S_ + j0 + jr) * D_ + h * DH_) + d4 * 4];
        }
        __syncthreads();
        int jend = i - j0; if (jend > 32) jend = 32;
        float pv = probs[w][j0 + lane];
        for (int jj = 0; jj < jend; jj++) {
            float wt = __shfl_sync(~0u, pv, jj);
            float2 vv = *(const float2*)&tile[jj][2 * lane];
            acc.x += wt * vv.x;
            acc.y += wt * vv.y;
        }
    }
    size_t ooff = ((size_t)(b * S_ + i) * D_ + h * DH_);
    if (i == 0) acc = make_float2(0.f, 0.f);   // zero_pad row 0
    *(float2*)&out[ooff + 2 * lane] = acc;
}

// ---------------- out = LayerNorm(xin + delta) * g + b ----------------
__global__ __launch_bounds__(128)
void resid_ln_kernel(const float* __restrict__ xin, const float* __restrict__ delta,
                     const float* __restrict__ g, const float* __restrict__ bta,
                     float* __restrict__ out) {
    __shared__ float red[4];
    int row = blockIdx.x;
    int t = threadIdx.x;
    float v[4];
    float s = 0.f;
    #pragma unroll
    for (int e = 0; e < 4; e++) {
        int d = t + e * 128;
        v[e] = xin[(size_t)row * D_ + d] + delta[(size_t)row * D_ + d];
        s += v[e];
    }
    for (int o = 16; o; o >>= 1) s += __shfl_xor_sync(~0u, s, o);
    if ((t & 31) == 0) red[t >> 5] = s;
    __syncthreads();
    s = red[0] + red[1] + red[2] + red[3];
    float mean = s * (1.f / D_);

    float sq = 0.f;
    #pragma unroll
    for (int e = 0; e < 4; e++) { float dd = v[e] - mean; sq += dd * dd; }
    __syncthreads();
    for (int o = 16; o; o >>= 1) sq += __shfl_xor_sync(~0u, sq, o);
    if ((t & 31) == 0) red[t >> 5] = sq;
    __syncthreads();
    sq = red[0] + red[1] + red[2] + red[3];
    float rstd = rsqrtf(sq * (1.f / D_) + 1e-5f);

    #pragma unroll
    for (int e = 0; e < 4; e++) {
        int d = t + e * 128;
        out[(size_t)row * D_ + d] = (v[e] - mean) * rstd * g[d] + bta[d];
    }
}

// ---------------- launcher ----------------
extern "C" void kernel_launch(void* const* d_in, const int* in_sizes, int n_in,
                              void* d_out, int out_size) {
    const float* question = (const float*)d_in[0];
    const float* inter    = (const float*)d_in[1];
    const float* pos      = (const float*)d_in[2];
    const float* Wk  = (const float*)d_in[3];
    const float* bk  = (const float*)d_in[4];
    const float* Wv  = (const float*)d_in[5];
    const float* bv  = (const float*)d_in[6];
    const float* Wo  = (const float*)d_in[7];
    const float* bo  = (const float*)d_in[8];
    const float* ln1g = (const float*)d_in[9];
    const float* ln1b = (const float*)d_in[10];
    const float* W1  = (const float*)d_in[11];
    const float* b1  = (const float*)d_in[12];
    const float* W2  = (const float*)d_in[13];
    const float* b2  = (const float*)d_in[14];
    const float* ln2g = (const float*)d_in[15];
    const float* ln2b = (const float*)d_in[16];

    float *x, *y, *qkb, *vb, *attnb, *tmpb, *ffb;
    cudaGetSymbolAddress((void**)&x,     g_x);
    cudaGetSymbolAddress((void**)&y,     g_y);
    cudaGetSymbolAddress((void**)&qkb,   g_qk);
    cudaGetSymbolAddress((void**)&vb,    g_v);
    cudaGetSymbolAddress((void**)&attnb, g_attn);
    cudaGetSymbolAddress((void**)&tmpb,  g_tmp);
    cudaGetSymbolAddress((void**)&ffb,   g_ff);

    cudaFuncSetAttribute(gemm_f16x3, cudaFuncAttributeMaxDynamicSharedMemorySize,
                         GSMEM_BYTES);

    add_pos_kernel<<<(B_ * S_ * D_) / 256, 256>>>(question, inter, pos);

    for (int l = 0; l < L_; l++) {
        const float* Wkl = Wk + (size_t)l * D_ * D_;
        const float* Wvl = Wv + (size_t)l * D_ * D_;
        const float* Wol = Wo + (size_t)l * D_ * D_;
        const float* W1l = W1 + (size_t)l * D_ * DFF_;
        const float* W2l = W2 + (size_t)l * DFF_ * D_;

        dim3 gD(D_ / 128, M_ / 128);       // 4 x 128
        dim3 gF(DFF_ / 128, M_ / 128);     // 16 x 128

        gemm_f16x3<<<gD, 256, GSMEM_BYTES>>>(x, Wkl, bk + l * D_, qkb, D_, D_, 0);
        gemm_f16x3<<<gD, 256, GSMEM_BYTES>>>(y, Wvl, bv + l * D_, vb,  D_, D_, 0);
        attn_kernel<<<B_ * H_ * (S_ / 8), dim3(32, 8)>>>(qkb, vb, attnb);
        gemm_f16x3<<<gD, 256, GSMEM_BYTES>>>(attnb, Wol, bo + l * D_, tmpb, D_, D_, 0);
        resid_ln_kernel<<<M_, 128>>>(x, tmpb, ln1g + l * D_, ln1b + l * D_, x);
        gemm_f16x3<<<gF, 256, GSMEM_BYTES>>>(x, W1l, b1 + l * DFF_, ffb, D_, DFF_, 1);
        gemm_f16x3<<<gD, 256, GSMEM_BYTES>>>(ffb, W2l, b2 + l * D_, tmpb, DFF_, D_, 0);
        float* lnout = (l == L_ - 1) ? (float*)d_out : x;
        resid_ln_kernel<<<M_, 128>>>(x, tmpb, ln2g + l * D_, ln2b + l * D_, lnout);
    }
}

// round 16
// speedup vs baseline: 2.1651x; 1.1497x over previous
#include <cuda_runtime.h>
#include <cuda_fp16.h>
#include <math.h>
#include <float.h>
#include <stdint.h>

#define L_    2
#define B_    32
#define S_    512
#define D_    512
#define H_    8
#define DH_   64
#define DFF_  2048
#define KIDX_ 5
#define M_    (B_*S_)   // 16384 rows

// ---------------- scratch (device globals; no runtime allocation) ----------------
__device__ float g_x[B_*S_*D_];
__device__ float g_y[B_*S_*D_];
__device__ float g_qk[B_*S_*D_];
__device__ float g_v[B_*S_*D_];
__device__ float g_attn[B_*S_*D_];
__device__ float g_tmp[B_*S_*D_];
__device__ float g_ff[(size_t)B_*S_*DFF_];

// ---------------- x = q_emb + pos ; y = i_emb + pos ----------------
__global__ void add_pos_kernel(const float* __restrict__ q,
                               const float* __restrict__ ie,
                               const float* __restrict__ pos) {
    int idx = blockIdx.x * blockDim.x + threadIdx.x;   // over B*S*D
    int sd  = idx % (S_ * D_);
    float p = pos[sd];
    g_x[idx] = q[idx]  + p;
    g_y[idx] = ie[idx] + p;
}

// ---------------- fp16 MMA helper ----------------
__device__ __forceinline__ void mma_f16(float* c, const unsigned* a, const unsigned* b) {
    asm volatile("mma.sync.aligned.m16n8k16.row.col.f32.f16.f16.f32 "
                 "{%0,%1,%2,%3}, {%4,%5,%6,%7}, {%8,%9}, {%0,%1,%2,%3};\n"
                 : "+f"(c[0]), "+f"(c[1]), "+f"(c[2]), "+f"(c[3])
                 : "r"(a[0]), "r"(a[1]), "r"(a[2]), "r"(a[3]),
                   "r"(b[0]), "r"(b[1]));
}

__device__ __forceinline__ unsigned packh2(__half a, __half b) {
    __half2 t = __halves2half2(a, b);
    return *(unsigned*)&t;
}

// split x = hi + lo (both fp16)
__device__ __forceinline__ void split2(float x, float y, __half2& h, __half2& l) {
    __half hx = __float2half_rn(x);
    __half hy = __float2half_rn(y);
    __half lx = __float2half_rn(x - __half2float(hx));
    __half ly = __float2half_rn(y - __half2float(hy));
    h = __halves2half2(hx, hy);
    l = __halves2half2(lx, ly);
}

// ---------------- 3xFP16 tensor-core GEMM ----------------
// C[M,N] = A[M,K] @ W[K,N] + bias (optional ReLU).
// CTA tile 128x128, BK=32, 8 warps (2x4), warp tile 64x32.
// SMEM stores k-adjacent half2 pairs: Ah/Al[k2][m], Bh/Bl[k2][n] (k2 = k/2).
// PADW=136 makes fragment LDS conflict-free (8*qa+g covers all banks).
#define BK_  32
#define NK2_ 16                 // BK/2
#define PADW 136                // row width in half2 (544B)
#define ARR_ (NK2_*PADW)        // 2176 half2 per array
#define BUFH (4*ARR_)           // Ah, Al, Bh, Bl
#define GSMEM_BYTES (2*BUFH*4)  // 69632 bytes

__global__ __launch_bounds__(256)
void gemm_f16x3(const float* __restrict__ A, const float* __restrict__ W,
                const float* __restrict__ bias, float* __restrict__ C,
                int K, int N, int relu) {
    extern __shared__ __align__(16) char smraw[];
    __half2* sm = (__half2*)smraw;

    int tid  = threadIdx.x;
    int lane = tid & 31, wid = tid >> 5;
    int qa   = lane & 3, g = lane >> 2;           // quad / group-row
    int warp_m = (wid >> 2) * 64;                 // 2 warps along M
    int warp_n = (wid & 3) * 32;                  // 4 warps along N
    int bm = blockIdx.y * 128, bn = blockIdx.x * 128;

    float acc[4][4][4];
    #pragma unroll
    for (int mt = 0; mt < 4; mt++)
        #pragma unroll
        for (int nt = 0; nt < 4; nt++)
            #pragma unroll
            for (int r = 0; r < 4; r++) acc[mt][nt][r] = 0.f;

    float4 rA[4], rW0[2], rW1[2];

    #pragma unroll
    for (int e = 0; e < 4; e++) {
        int idx = tid + e * 256;
        int m = idx & 127, k4 = idx >> 7;
        rA[e] = *(const float4*)&A[(size_t)(bm + m) * K + k4 * 4];
    }
    #pragma unroll
    for (int e = 0; e < 2; e++) {
        int idx = tid + e * 256;
        int k2 = idx >> 5, n4 = idx & 31;
        rW0[e] = *(const float4*)&W[(size_t)(2 * k2)     * N + bn + n4 * 4];
        rW1[e] = *(const float4*)&W[(size_t)(2 * k2 + 1) * N + bn + n4 * 4];
    }

    int NT = K / BK_;
    for (int kt = 0; kt < NT; kt++) {
        __half2* Ah = sm + (kt & 1) * BUFH;
        __half2* Al = Ah + ARR_;
        __half2* Bh = Al + ARR_;
        __half2* Bl = Bh + ARR_;

        #pragma unroll
        for (int e = 0; e < 4; e++) {
            int idx = tid + e * 256;
            int m = idx & 127, k4 = idx >> 7;
            __half2 h0, l0, h1, l1;
            split2(rA[e].x, rA[e].y, h0, l0);
            split2(rA[e].z, rA[e].w, h1, l1);
            Ah[(2 * k4)     * PADW + m] = h0;
            Ah[(2 * k4 + 1) * PADW + m] = h1;
            Al[(2 * k4)     * PADW + m] = l0;
            Al[(2 * k4 + 1) * PADW + m] = l1;
        }
        #pragma unroll
        for (int e = 0; e < 2; e++) {
            int idx = tid + e * 256;
            int k2 = idx >> 5, n4 = idx & 31;
            const float* p0 = (const float*)&rW0[e];
            const float* p1 = (const float*)&rW1[e];
            __half2 hh[4], ll[4];
            #pragma unroll
            for (int j = 0; j < 4; j++) {
                __half h0 = __float2half_rn(p0[j]);
                __half h1 = __float2half_rn(p1[j]);
                __half l0 = __float2half_rn(p0[j] - __half2float(h0));
                __half l1 = __float2half_rn(p1[j] - __half2float(h1));
                hh[j] = __halves2half2(h0, h1);
                ll[j] = __halves2half2(l0, l1);
            }
            *(uint4*)&Bh[k2 * PADW + n4 * 4] = *(uint4*)hh;
            *(uint4*)&Bl[k2 * PADW + n4 * 4] = *(uint4*)ll;
        }
        __syncthreads();

        if (kt + 1 < NT) {
            int k0n = (kt + 1) * BK_;
            #pragma unroll
            for (int e = 0; e < 4; e++) {
                int idx = tid + e * 256;
                int m = idx & 127, k4 = idx >> 7;
                rA[e] = *(const float4*)&A[(size_t)(bm + m) * K + k0n + k4 * 4];
            }
            #pragma unroll
            for (int e = 0; e < 2; e++) {
                int idx = tid + e * 256;
                int k2 = idx >> 5, n4 = idx & 31;
                rW0[e] = *(const float4*)&W[(size_t)(k0n + 2 * k2)     * N + bn + n4 * 4];
                rW1[e] = *(const float4*)&W[(size_t)(k0n + 2 * k2 + 1) * N + bn + n4 * 4];
            }
        }

        #pragma unroll
        for (int s = 0; s < 2; s++) {
            int s8 = s * 8;
            unsigned bh[4][2], bl[4][2];
            #pragma unroll
            for (int nt = 0; nt < 4; nt++) {
                int nb = warp_n + nt * 8 + g;
                bh[nt][0] = *(const unsigned*)&Bh[(s8 + qa)     * PADW + nb];
                bh[nt][1] = *(const unsigned*)&Bh[(s8 + qa + 4) * PADW + nb];
                bl[nt][0] = *(const unsigned*)&Bl[(s8 + qa)     * PADW + nb];
                bl[nt][1] = *(const unsigned*)&Bl[(s8 + qa + 4) * PADW + nb];
            }
            #pragma unroll
            for (int mt = 0; mt < 4; mt++) {
                int rm = warp_m + mt * 16 + g;
                unsigned ah[4], al[4];
                ah[0] = *(const unsigned*)&Ah[(s8 + qa)     * PADW + rm];
                ah[1] = *(const unsigned*)&Ah[(s8 + qa)     * PADW + rm + 8];
                ah[2] = *(const unsigned*)&Ah[(s8 + qa + 4) * PADW + rm];
                ah[3] = *(const unsigned*)&Ah[(s8 + qa + 4) * PADW + rm + 8];
                al[0] = *(const unsigned*)&Al[(s8 + qa)     * PADW + rm];
                al[1] = *(const unsigned*)&Al[(s8 + qa)     * PADW + rm + 8];
                al[2] = *(const unsigned*)&Al[(s8 + qa + 4) * PADW + rm];
                al[3] = *(const unsigned*)&Al[(s8 + qa + 4) * PADW + rm + 8];
                #pragma unroll
                for (int nt = 0; nt < 4; nt++) {
                    mma_f16(acc[mt][nt], al, bh[nt]);   // lo*hi
                    mma_f16(acc[mt][nt], ah, bl[nt]);   // hi*lo
                    mma_f16(acc[mt][nt], ah, bh[nt]);   // hi*hi
                }
            }
        }
        __syncthreads();
    }

    #pragma unroll
    for (int mt = 0; mt < 4; mt++) {
        #pragma unroll
        for (int nt = 0; nt < 4; nt++) {
            int row = bm + warp_m + mt * 16 + g;
            int col = bn + warp_n + nt * 8 + 2 * qa;
            float2 bb = *(const float2*)&bias[col];
            float o0 = acc[mt][nt][0] + bb.x;
            float o1 = acc[mt][nt][1] + bb.y;
            float o2 = acc[mt][nt][2] + bb.x;
            float o3 = acc[mt][nt][3] + bb.y;
            if (relu) {
                o0 = fmaxf(o0, 0.f); o1 = fmaxf(o1, 0.f);
                o2 = fmaxf(o2, 0.f); o3 = fmaxf(o3, 0.f);
            }
            *(float2*)&C[(size_t)row * N + col]       = make_float2(o0, o1);
            *(float2*)&C[(size_t)(row + 8) * N + col] = make_float2(o2, o3);
        }
    }
}

// ---------------- MMA sparse causal attention ----------------
// Block: 8 query rows (one (b,h)); 8 warps. Tiles of 32 keys, double-buffered.
// QK: warps 0-3 do 3-split m16n8k16 MMA (Q regs x K smem), warps 4-7 fill next K.
// Softmax/top-k: per-warp on pb[w][512] (same logic as scalar version).
// PV: all 8 warps, warp w owns d-tile w (8 cols), accumulate over key tiles.
#define KST 40     // K tile row stride (half2)
#define VST 73     // V tile row stride (half2)
#define PBH 520    // pH/pL row stride (halves)
// smem offsets (bytes)
#define AOFF_SC 20480
#define AOFF_PB 21568
#define AOFF_PH 37952
#define AOFF_PL 46272
#define ASMEM_BYTES 54592

__device__ __forceinline__ void fillK(__half2* Kh, __half2* Kl,
                                      const float* __restrict__ qk,
                                      int b, int h, int j0, int tid) {
    int lane = tid & 31;
    int wq = (tid >> 5) - 4;                    // 0..3
    #pragma unroll
    for (int e = 0; e < 4; e++) {
        int dd4 = wq + 4 * e;                   // 0..15
        const float* src = &qk[((size_t)(b * S_ + j0 + lane)) * D_ + h * DH_ + dd4 * 4];
        float4 kv = *(const float4*)src;
        __half2 h0, l0, h1, l1;
        split2(kv.x, kv.y, h0, l0);
        split2(kv.z, kv.w, h1, l1);
        Kh[(2 * dd4)     * KST + lane] = h0;
        Kh[(2 * dd4 + 1) * KST + lane] = h1;
        Kl[(2 * dd4)     * KST + lane] = l0;
        Kl[(2 * dd4 + 1) * KST + lane] = l1;
    }
}

__device__ __forceinline__ void fillV(__half2* Vh, __half2* Vl,
                                      const float* __restrict__ v,
                                      int b, int h, int j0, int tid) {
    int j2 = tid >> 4, d4 = tid & 15;           // 16 x 16 = 256 items
    const float* s0 = &v[((size_t)(b * S_ + j0 + 2 * j2))     * D_ + h * DH_ + d4 * 4];
    const float* s1 = &v[((size_t)(b * S_ + j0 + 2 * j2 + 1)) * D_ + h * DH_ + d4 * 4];
    float4 v0 = *(const float4*)s0;
    float4 v1 = *(const float4*)s1;
    const float* a0 = (const float*)&v0;
    const float* a1 = (const float*)&v1;
    #pragma unroll
    for (int u = 0; u < 4; u++) {
        __half hj0 = __float2half_rn(a0[u]);
        __half hj1 = __float2half_rn(a1[u]);
        __half lj0 = __float2half_rn(a0[u] - __half2float(hj0));
        __half lj1 = __float2half_rn(a1[u] - __half2float(hj1));
        Vh[j2 * VST + d4 * 4 + u] = __halves2half2(hj0, hj1);   // (row 2j2, row 2j2+1)
        Vl[j2 * VST + d4 * 4 + u] = __halves2half2(lj0, lj1);
    }
}

__global__ __launch_bounds__(256)
void attn_kernel(const float* __restrict__ qk, const float* __restrict__ v,
                 float* __restrict__ out) {
    extern __shared__ __align__(16) char sm[];
    __half2* tb = (__half2*)sm;                        // K/V tile union
    float*   sc = (float*)(sm + AOFF_SC);              // [8][34]
    float*   pb = (float*)(sm + AOFF_PB);              // [8][512]
    __half*  pH = (__half*)(sm + AOFF_PH);             // [8][520]
    __half*  pL = (__half*)(sm + AOFF_PL);             // [8][520]

    int tid = threadIdx.x, lane = tid & 31, wid = tid >> 5;
    int qa = lane & 3, g = lane >> 2;
    int blk = blockIdx.x;
    int bh = blk >> 6, i0 = (blk & 63) * 8;
    int b = bh >> 3, h = bh & 7;
    int i = i0 + wid;                                  // this warp's query row
    int ntiles = (i0 + 7 + 31) >> 5;

    // ---- Q fragments into registers (warps 0-3) + prefill K tile 0 (warps 4-7) ----
    unsigned qfh[4][2], qfl[4][2];
    if (wid < 4) {
        size_t qrow = ((size_t)(b * S_ + i0 + g)) * D_ + h * DH_;
        #pragma unroll
        for (int s = 0; s < 4; s++) {
            float2 f0 = *(const float2*)&qk[qrow + s * 16 + 2 * qa];
            float2 f1 = *(const float2*)&qk[qrow + s * 16 + 2 * qa + 8];
            __half2 hh, ll;
            split2(f0.x, f0.y, hh, ll);
            qfh[s][0] = *(unsigned*)&hh; qfl[s][0] = *(unsigned*)&ll;
            split2(f1.x, f1.y, hh, ll);
            qfh[s][1] = *(unsigned*)&hh; qfl[s][1] = *(unsigned*)&ll;
        }
    } else {
        fillK(tb, tb + 1280, qk, b, h, 0, tid);
    }
    __syncthreads();

    // ---- phase 1: QK scores via MMA ----
    for (int t = 0; t < ntiles; t++) {
        if (wid < 4) {
            __half2* Kh = tb + (t & 1) * 2560;
            __half2* Kl = Kh + 1280;
            int n = wid * 8 + g;
            float c[4] = {0.f, 0.f, 0.f, 0.f};
            #pragma unroll
            for (int s = 0; s < 4; s++) {
                unsigned Bhf[2], Blf[2];
                Bhf[0] = *(const unsigned*)&Kh[(s * 8 + qa)     * KST + n];
                Bhf[1] = *(const unsigned*)&Kh[(s * 8 + qa + 4) * KST + n];
                Blf[0] = *(const unsigned*)&Kl[(s * 8 + qa)     * KST + n];
                Blf[1] = *(const unsigned*)&Kl[(s * 8 + qa + 4) * KST + n];
                unsigned Af_h[4] = {qfh[s][0], 0u, qfh[s][1], 0u};
                unsigned Af_l[4] = {qfl[s][0], 0u, qfl[s][1], 0u};
                mma_f16(c, Af_l, Bhf);
                mma_f16(c, Af_h, Blf);
                mma_f16(c, Af_h, Bhf);
            }
            *(float2*)&sc[g * 34 + wid * 8 + 2 * qa] = make_float2(c[0], c[1]);
        } else if (t + 1 < ntiles) {
            __half2* Kh = tb + ((t + 1) & 1) * 2560;
            fillK(Kh, Kh + 1280, qk, b, h, (t + 1) * 32, tid);
        }
        __syncthreads();
        {
            int j = t * 32 + lane;
            float raw = sc[wid * 34 + lane];
            pb[wid * 512 + j] = (j < i) ? raw * 0.125f : 0.f;
        }
        __syncthreads();
    }

    // ---- phase 2+3: softmax + top-k re-softmax (per warp on pb row) ----
    float* prow = pb + wid * 512;
    if (i > 0) {
        float mx = -FLT_MAX;
        for (int j = lane; j < i; j += 32) mx = fmaxf(mx, prow[j]);
        for (int o = 16; o; o >>= 1) mx = fmaxf(mx, __shfl_xor_sync(~0u, mx, o));
        float sum = 0.f;
        for (int j = lane; j < i; j += 32) {
            float e = expf(prow[j] - mx);
            prow[j] = e; sum += e;
        }
        for (int o = 16; o; o >>= 1) sum += __shfl_xor_sync(~0u, sum, o);
        float inv = 1.f / sum;
        for (int j = lane; j < i; j += 32) prow[j] *= inv;

        if (i > KIDX_) {
            float cur = FLT_MAX;
            int kept = 0;
            float m1 = -FLT_MAX;
            for (int it = 0; it < KIDX_ && kept < KIDX_; it++) {
                float lm = -FLT_MAX;
                for (int j = lane; j < i; j += 32) {
                    float p = prow[j];
                    if (p < cur && p > lm) lm = p;
                }
                for (int o = 16; o; o >>= 1) lm = fmaxf(lm, __shfl_xor_sync(~0u, lm, o));
                int lc = 0;
                for (int j = lane; j < i; j += 32) if (prow[j] == lm) lc++;
                for (int o = 16; o; o >>= 1) lc += __shfl_xor_sync(~0u, lc, o);
                if (it == 0) m1 = lm;
                kept += lc;
                cur = lm;
            }
            float thresh = cur;
            float sum2 = 0.f;
            for (int j = lane; j < i; j += 32) {
                float p = prow[j];
                float wt = (p >= thresh) ? expf(p - m1) : 0.f;
                prow[j] = wt; sum2 += wt;
            }
            for (int o = 16; o; o >>= 1) sum2 += __shfl_xor_sync(~0u, sum2, o);
            float inv2 = 1.f / sum2;
            for (int j = lane; j < i; j += 32) prow[j] *= inv2;
        }
    }
    // invalid entries (j >= i) are 0 in pb; for i==0 the whole row is 0 (zero_pad).
    __syncthreads();

    // ---- convert probs to hi/lo fp16 ----
    for (int k = 0; k < ntiles; k++) {
        int j = k * 32 + lane;
        float p = prow[j];
        __half hp = __float2half_rn(p);
        pH[wid * PBH + j] = hp;
        pL[wid * PBH + j] = __float2half_rn(p - __half2float(hp));
    }
    __syncthreads();

    // ---- phase 4: PV via MMA; warp w owns d-tile w (8 cols), accumulates over tiles ----
    fillV(tb, tb + 1168, v, b, h, 0, tid);
    float c[4] = {0.f, 0.f, 0.f, 0.f};
    __syncthreads();

    for (int t = 0; t < ntiles; t++) {
        __half2* Vh = tb + (t & 1) * 2336;
        __half2* Vl = Vh + 1168;
        int n = wid * 8 + g;
        #pragma unroll
        for (int s = 0; s < 2; s++) {
            int jb = t * 32 + s * 16;
            unsigned a0h = *(const unsigned*)&pH[g * PBH + jb + 2 * qa];
            unsigned a2h = *(const unsigned*)&pH[g * PBH + jb + 2 * qa + 8];
            unsigned a0l = *(const unsigned*)&pL[g * PBH + jb + 2 * qa];
            unsigned a2l = *(const unsigned*)&pL[g * PBH + jb + 2 * qa + 8];
            unsigned Bhf[2], Blf[2];
            Bhf[0] = *(const unsigned*)&Vh[(s * 8 + qa)     * VST + n];
            Bhf[1] = *(const unsigned*)&Vh[(s * 8 + qa + 4) * VST + n];
            Blf[0] = *(const unsigned*)&Vl[(s * 8 + qa)     * VST + n];
            Blf[1] = *(const unsigned*)&Vl[(s * 8 + qa + 4) * VST + n];
            unsigned Af_h[4] = {a0h, 0u, a2h, 0u};
            unsigned Af_l[4] = {a0l, 0u, a2l, 0u};
            mma_f16(c, Af_l, Bhf);
            mma_f16(c, Af_h, Blf);
            mma_f16(c, Af_h, Bhf);
        }
        if (t + 1 < ntiles) {
            __half2* nVh = tb + ((t + 1) & 1) * 2336;
            fillV(nVh, nVh + 1168, v, b, h, (t + 1) * 32, tid);
        }
        __syncthreads();
    }

    // epilogue: row g (query i0+g), cols wid*8 + 2qa (+1). c2/c3 (rows g+8) unused.
    size_t orow = ((size_t)(b * S_ + i0 + g)) * D_ + h * DH_ + wid * 8 + 2 * qa;
    *(float2*)&out[orow] = make_float2(c[0], c[1]);
}

// ---------------- out = LayerNorm(xin + delta) * g + b ----------------
__global__ __launch_bounds__(128)
void resid_ln_kernel(const float* __restrict__ xin, const float* __restrict__ delta,
                     const float* __restrict__ g, const float* __restrict__ bta,
                     float* __restrict__ out) {
    __shared__ float red[4];
    int row = blockIdx.x;
    int t = threadIdx.x;
    float v[4];
    float s = 0.f;
    #pragma unroll
    for (int e = 0; e < 4; e++) {
        int d = t + e * 128;
        v[e] = xin[(size_t)row * D_ + d] + delta[(size_t)row * D_ + d];
        s += v[e];
    }
    for (int o = 16; o; o >>= 1) s += __shfl_xor_sync(~0u, s, o);
    if ((t & 31) == 0) red[t >> 5] = s;
    __syncthreads();
    s = red[0] + red[1] + red[2] + red[3];
    float mean = s * (1.f / D_);

    float sq = 0.f;
    #pragma unroll
    for (int e = 0; e < 4; e++) { float dd = v[e] - mean; sq += dd * dd; }
    __syncthreads();
    for (int o = 16; o; o >>= 1) sq += __shfl_xor_sync(~0u, sq, o);
    if ((t & 31) == 0) red[t >> 5] = sq;
    __syncthreads();
    sq = red[0] + red[1] + red[2] + red[3];
    float rstd = rsqrtf(sq * (1.f / D_) + 1e-5f);

    #pragma unroll
    for (int e = 0; e < 4; e++) {
        int d = t + e * 128;
        out[(size_t)row * D_ + d] = (v[e] - mean) * rstd * g[d] + bta[d];
    }
}

// ---------------- launcher ----------------
extern "C" void kernel_launch(void* const* d_in, const int* in_sizes, int n_in,
                              void* d_out, int out_size) {
    const float* question = (const float*)d_in[0];
    const float* inter    = (const float*)d_in[1];
    const float* pos      = (const float*)d_in[2];
    const float* Wk  = (const float*)d_in[3];
    const float* bk  = (const float*)d_in[4];
    const float* Wv  = (const float*)d_in[5];
    const float* bv  = (const float*)d_in[6];
    const float* Wo  = (const float*)d_in[7];
    const float* bo  = (const float*)d_in[8];
    const float* ln1g = (const float*)d_in[9];
    const float* ln1b = (const float*)d_in[10];
    const float* W1  = (const float*)d_in[11];
    const float* b1  = (const float*)d_in[12];
    const float* W2  = (const float*)d_in[13];
    const float* b2  = (const float*)d_in[14];
    const float* ln2g = (const float*)d_in[15];
    const float* ln2b = (const float*)d_in[16];

    float *x, *y, *qkb, *vb, *attnb, *tmpb, *ffb;
    cudaGetSymbolAddress((void**)&x,     g_x);
    cudaGetSymbolAddress((void**)&y,     g_y);
    cudaGetSymbolAddress((void**)&qkb,   g_qk);
    cudaGetSymbolAddress((void**)&vb,    g_v);
    cudaGetSymbolAddress((void**)&attnb, g_attn);
    cudaGetSymbolAddress((void**)&tmpb,  g_tmp);
    cudaGetSymbolAddress((void**)&ffb,   g_ff);

    cudaFuncSetAttribute(gemm_f16x3, cudaFuncAttributeMaxDynamicSharedMemorySize,
                         GSMEM_BYTES);
    cudaFuncSetAttribute(attn_kernel, cudaFuncAttributeMaxDynamicSharedMemorySize,
                         ASMEM_BYTES);

    add_pos_kernel<<<(B_ * S_ * D_) / 256, 256>>>(question, inter, pos);

    for (int l = 0; l < L_; l++) {
        const float* Wkl = Wk + (size_t)l * D_ * D_;
        const float* Wvl = Wv + (size_t)l * D_ * D_;
        const float* Wol = Wo + (size_t)l * D_ * D_;
        const float* W1l = W1 + (size_t)l * D_ * DFF_;
        const float* W2l = W2 + (size_t)l * DFF_ * D_;

        dim3 gD(D_ / 128, M_ / 128);       // 4 x 128
        dim3 gF(DFF_ / 128, M_ / 128);     // 16 x 128

        gemm_f16x3<<<gD, 256, GSMEM_BYTES>>>(x, Wkl, bk + l * D_, qkb, D_, D_, 0);
        gemm_f16x3<<<gD, 256, GSMEM_BYTES>>>(y, Wvl, bv + l * D_, vb,  D_, D_, 0);
        attn_kernel<<<B_ * H_ * (S_ / 8), 256, ASMEM_BYTES>>>(qkb, vb, attnb);
        gemm_f16x3<<<gD, 256, GSMEM_BYTES>>>(attnb, Wol, bo + l * D_, tmpb, D_, D_, 0);
        resid_ln_kernel<<<M_, 128>>>(x, tmpb, ln1g + l * D_, ln1b + l * D_, x);
        gemm_f16x3<<<gF, 256, GSMEM_BYTES>>>(x, W1l, b1 + l * DFF_, ffb, D_, DFF_, 1);
        gemm_f16x3<<<gD, 256, GSMEM_BYTES>>>(ffb, W2l, b2 + l * D_, tmpb, DFF_, D_, 0);
        float* lnout = (l == L_ - 1) ? (float*)d_out : x;
        resid_ln_kernel<<<M_, 128>>>(x, tmpb, ln2g + l * D_, ln2b + l * D_, lnout);
    }
}

// round 17
// speedup vs baseline: 2.4429x; 1.1283x over previous
#include <cuda_runtime.h>
#include <cuda_fp16.h>
#include <math.h>
#include <float.h>
#include <stdint.h>

#define L_    2
#define B_    32
#define S_    512
#define D_    512
#define H_    8
#define DH_   64
#define DFF_  2048
#define KIDX_ 5
#define M_    (B_*S_)   // 16384 rows

// ---------------- scratch (device globals; no runtime allocation) ----------------
__device__ float g_x[B_*S_*D_];
__device__ float g_y[B_*S_*D_];
__device__ float g_qk[B_*S_*D_];
__device__ float g_v[B_*S_*D_];
__device__ float g_attn[B_*S_*D_];
__device__ float g_tmp[B_*S_*D_];
__device__ float g_ff[(size_t)B_*S_*DFF_];

// ---------------- x = q_emb + pos ; y = i_emb + pos ----------------
__global__ void add_pos_kernel(const float* __restrict__ q,
                               const float* __restrict__ ie,
                               const float* __restrict__ pos) {
    int idx = blockIdx.x * blockDim.x + threadIdx.x;   // over B*S*D
    int sd  = idx % (S_ * D_);
    float p = pos[sd];
    g_x[idx] = q[idx]  + p;
    g_y[idx] = ie[idx] + p;
}

// ---------------- fp16 MMA helper ----------------
__device__ __forceinline__ void mma_f16(float* c, const unsigned* a, const unsigned* b) {
    asm volatile("mma.sync.aligned.m16n8k16.row.col.f32.f16.f16.f32 "
                 "{%0,%1,%2,%3}, {%4,%5,%6,%7}, {%8,%9}, {%0,%1,%2,%3};\n"
                 : "+f"(c[0]), "+f"(c[1]), "+f"(c[2]), "+f"(c[3])
                 : "r"(a[0]), "r"(a[1]), "r"(a[2]), "r"(a[3]),
                   "r"(b[0]), "r"(b[1]));
}

// split x = hi + lo (both fp16)
__device__ __forceinline__ void split2(float x, float y, __half2& h, __half2& l) {
    __half hx = __float2half_rn(x);
    __half hy = __float2half_rn(y);
    __half lx = __float2half_rn(x - __half2float(hx));
    __half ly = __float2half_rn(y - __half2float(hy));
    h = __halves2half2(hx, hy);
    l = __halves2half2(lx, ly);
}

// ---------------- 3xFP16 tensor-core GEMM (unchanged, passing) ----------------
#define BK_  32
#define NK2_ 16                 // BK/2
#define PADW 136                // row width in half2 (544B)
#define ARR_ (NK2_*PADW)        // 2176 half2 per array
#define BUFH (4*ARR_)           // Ah, Al, Bh, Bl
#define GSMEM_BYTES (2*BUFH*4)  // 69632 bytes

__global__ __launch_bounds__(256)
void gemm_f16x3(const float* __restrict__ A, const float* __restrict__ W,
                const float* __restrict__ bias, float* __restrict__ C,
                int K, int N, int relu) {
    extern __shared__ __align__(16) char smraw[];
    __half2* sm = (__half2*)smraw;

    int tid  = threadIdx.x;
    int lane = tid & 31, wid = tid >> 5;
    int qa   = lane & 3, g = lane >> 2;
    int warp_m = (wid >> 2) * 64;
    int warp_n = (wid & 3) * 32;
    int bm = blockIdx.y * 128, bn = blockIdx.x * 128;

    float acc[4][4][4];
    #pragma unroll
    for (int mt = 0; mt < 4; mt++)
        #pragma unroll
        for (int nt = 0; nt < 4; nt++)
            #pragma unroll
            for (int r = 0; r < 4; r++) acc[mt][nt][r] = 0.f;

    float4 rA[4], rW0[2], rW1[2];

    #pragma unroll
    for (int e = 0; e < 4; e++) {
        int idx = tid + e * 256;
        int m = idx & 127, k4 = idx >> 7;
        rA[e] = *(const float4*)&A[(size_t)(bm + m) * K + k4 * 4];
    }
    #pragma unroll
    for (int e = 0; e < 2; e++) {
        int idx = tid + e * 256;
        int k2 = idx >> 5, n4 = idx & 31;
        rW0[e] = *(const float4*)&W[(size_t)(2 * k2)     * N + bn + n4 * 4];
        rW1[e] = *(const float4*)&W[(size_t)(2 * k2 + 1) * N + bn + n4 * 4];
    }

    int NT = K / BK_;
    for (int kt = 0; kt < NT; kt++) {
        __half2* Ah = sm + (kt & 1) * BUFH;
        __half2* Al = Ah + ARR_;
        __half2* Bh = Al + ARR_;
        __half2* Bl = Bh + ARR_;

        #pragma unroll
        for (int e = 0; e < 4; e++) {
            int idx = tid + e * 256;
            int m = idx & 127, k4 = idx >> 7;
            __half2 h0, l0, h1, l1;
            split2(rA[e].x, rA[e].y, h0, l0);
            split2(rA[e].z, rA[e].w, h1, l1);
            Ah[(2 * k4)     * PADW + m] = h0;
            Ah[(2 * k4 + 1) * PADW + m] = h1;
            Al[(2 * k4)     * PADW + m] = l0;
            Al[(2 * k4 + 1) * PADW + m] = l1;
        }
        #pragma unroll
        for (int e = 0; e < 2; e++) {
            int idx = tid + e * 256;
            int k2 = idx >> 5, n4 = idx & 31;
            const float* p0 = (const float*)&rW0[e];
            const float* p1 = (const float*)&rW1[e];
            __half2 hh[4], ll[4];
            #pragma unroll
            for (int j = 0; j < 4; j++) {
                __half h0 = __float2half_rn(p0[j]);
                __half h1 = __float2half_rn(p1[j]);
                __half l0 = __float2half_rn(p0[j] - __half2float(h0));
                __half l1 = __float2half_rn(p1[j] - __half2float(h1));
                hh[j] = __halves2half2(h0, h1);
                ll[j] = __halves2half2(l0, l1);
            }
            *(uint4*)&Bh[k2 * PADW + n4 * 4] = *(uint4*)hh;
            *(uint4*)&Bl[k2 * PADW + n4 * 4] = *(uint4*)ll;
        }
        __syncthreads();

        if (kt + 1 < NT) {
            int k0n = (kt + 1) * BK_;
            #pragma unroll
            for (int e = 0; e < 4; e++) {
                int idx = tid + e * 256;
                int m = idx & 127, k4 = idx >> 7;
                rA[e] = *(const float4*)&A[(size_t)(bm + m) * K + k0n + k4 * 4];
            }
            #pragma unroll
            for (int e = 0; e < 2; e++) {
                int idx = tid + e * 256;
                int k2 = idx >> 5, n4 = idx & 31;
                rW0[e] = *(const float4*)&W[(size_t)(k0n + 2 * k2)     * N + bn + n4 * 4];
                rW1[e] = *(const float4*)&W[(size_t)(k0n + 2 * k2 + 1) * N + bn + n4 * 4];
            }
        }

        #pragma unroll
        for (int s = 0; s < 2; s++) {
            int s8 = s * 8;
            unsigned bh[4][2], bl[4][2];
            #pragma unroll
            for (int nt = 0; nt < 4; nt++) {
                int nb = warp_n + nt * 8 + g;
                bh[nt][0] = *(const unsigned*)&Bh[(s8 + qa)     * PADW + nb];
                bh[nt][1] = *(const unsigned*)&Bh[(s8 + qa + 4) * PADW + nb];
                bl[nt][0] = *(const unsigned*)&Bl[(s8 + qa)     * PADW + nb];
                bl[nt][1] = *(const unsigned*)&Bl[(s8 + qa + 4) * PADW + nb];
            }
            #pragma unroll
            for (int mt = 0; mt < 4; mt++) {
                int rm = warp_m + mt * 16 + g;
                unsigned ah[4], al[4];
                ah[0] = *(const unsigned*)&Ah[(s8 + qa)     * PADW + rm];
                ah[1] = *(const unsigned*)&Ah[(s8 + qa)     * PADW + rm + 8];
                ah[2] = *(const unsigned*)&Ah[(s8 + qa + 4) * PADW + rm];
                ah[3] = *(const unsigned*)&Ah[(s8 + qa + 4) * PADW + rm + 8];
                al[0] = *(const unsigned*)&Al[(s8 + qa)     * PADW + rm];
                al[1] = *(const unsigned*)&Al[(s8 + qa)     * PADW + rm + 8];
                al[2] = *(const unsigned*)&Al[(s8 + qa + 4) * PADW + rm];
                al[3] = *(const unsigned*)&Al[(s8 + qa + 4) * PADW + rm + 8];
                #pragma unroll
                for (int nt = 0; nt < 4; nt++) {
                    mma_f16(acc[mt][nt], al, bh[nt]);
                    mma_f16(acc[mt][nt], ah, bl[nt]);
                    mma_f16(acc[mt][nt], ah, bh[nt]);
                }
            }
        }
        __syncthreads();
    }

    #pragma unroll
    for (int mt = 0; mt < 4; mt++) {
        #pragma unroll
        for (int nt = 0; nt < 4; nt++) {
            int row = bm + warp_m + mt * 16 + g;
            int col = bn + warp_n + nt * 8 + 2 * qa;
            float2 bb = *(const float2*)&bias[col];
            float o0 = acc[mt][nt][0] + bb.x;
            float o1 = acc[mt][nt][1] + bb.y;
            float o2 = acc[mt][nt][2] + bb.x;
            float o3 = acc[mt][nt][3] + bb.y;
            if (relu) {
                o0 = fmaxf(o0, 0.f); o1 = fmaxf(o1, 0.f);
                o2 = fmaxf(o2, 0.f); o3 = fmaxf(o3, 0.f);
            }
            *(float2*)&C[(size_t)row * N + col]       = make_float2(o0, o1);
            *(float2*)&C[(size_t)(row + 8) * N + col] = make_float2(o2, o3);
        }
    }
}

// ---------------- MMA sparse causal attention (16 queries/block) ----------------
// Block: 16 query rows of one (b,h); 8 warps. 32-key tiles, double-buffered.
// QK: warps 0-3 full-m16 3-split MMA; warps 4-7 prefetch next K tile.
// Softmax/top-k: register-resident (warp w owns rows w and w+8).
// PV: all warps, warp w owns 8-col d-tile; all 4 C-frag rows used.
#define KST 40     // K tile row stride (half2)
#define VST 73     // V tile row stride (half2)
#define PBH 520    // pH/pL row stride (halves)
#define AOFF_SC 20480
#define AOFF_PH (AOFF_SC + 16*34*4)        // 22656
#define AOFF_PL (AOFF_PH + 16*PBH*2)       // 39296
#define ASMEM_BYTES (AOFF_PL + 16*PBH*2)   // 55936

__device__ __forceinline__ void fillK(__half2* Kh, __half2* Kl,
                                      const float* __restrict__ qk,
                                      int b, int h, int j0, int tid) {
    int lane = tid & 31;
    int wq = (tid >> 5) - 4;                    // 0..3
    #pragma unroll
    for (int e = 0; e < 4; e++) {
        int dd4 = wq + 4 * e;                   // 0..15
        const float* src = &qk[((size_t)(b * S_ + j0 + lane)) * D_ + h * DH_ + dd4 * 4];
        float4 kv = *(const float4*)src;
        __half2 h0, l0, h1, l1;
        split2(kv.x, kv.y, h0, l0);
        split2(kv.z, kv.w, h1, l1);
        Kh[(2 * dd4)     * KST + lane] = h0;
        Kh[(2 * dd4 + 1) * KST + lane] = h1;
        Kl[(2 * dd4)     * KST + lane] = l0;
        Kl[(2 * dd4 + 1) * KST + lane] = l1;
    }
}

__device__ __forceinline__ void fillV(__half2* Vh, __half2* Vl,
                                      const float* __restrict__ v,
                                      int b, int h, int j0, int tid) {
    int j2 = tid >> 4, d4 = tid & 15;           // 16 x 16 = 256 items
    const float* s0 = &v[((size_t)(b * S_ + j0 + 2 * j2))     * D_ + h * DH_ + d4 * 4];
    const float* s1 = &v[((size_t)(b * S_ + j0 + 2 * j2 + 1)) * D_ + h * DH_ + d4 * 4];
    float4 v0 = *(const float4*)s0;
    float4 v1 = *(const float4*)s1;
    const float* a0 = (const float*)&v0;
    const float* a1 = (const float*)&v1;
    #pragma unroll
    for (int u = 0; u < 4; u++) {
        __half hj0 = __float2half_rn(a0[u]);
        __half hj1 = __float2half_rn(a1[u]);
        __half lj0 = __float2half_rn(a0[u] - __half2float(hj0));
        __half lj1 = __float2half_rn(a1[u] - __half2float(hj1));
        Vh[j2 * VST + d4 * 4 + u] = __halves2half2(hj0, hj1);
        Vl[j2 * VST + d4 * 4 + u] = __halves2half2(lj0, lj1);
    }
}

// register softmax + top-k over pr[0..nt-1] (entries invalid -> -1e30f)
__device__ __forceinline__ void reg_softmax(float* pr, int nt, int i, int lane) {
    if (i <= 0) return;
    float mx = -FLT_MAX;
    #pragma unroll
    for (int t = 0; t < 16; t++) if (t < nt) mx = fmaxf(mx, pr[t]);
    for (int o = 16; o; o >>= 1) mx = fmaxf(mx, __shfl_xor_sync(~0u, mx, o));
    float sum = 0.f;
    #pragma unroll
    for (int t = 0; t < 16; t++) if (t < nt) {
        float e = expf(pr[t] - mx);
        pr[t] = e; sum += e;
    }
    for (int o = 16; o; o >>= 1) sum += __shfl_xor_sync(~0u, sum, o);
    float inv = 1.f / sum;
    #pragma unroll
    for (int t = 0; t < 16; t++) if (t < nt) pr[t] *= inv;

    if (i > KIDX_) {
        float cur = FLT_MAX;
        int kept = 0;
        float m1 = -FLT_MAX;
        for (int it = 0; it < KIDX_ && kept < KIDX_; it++) {
            float lm = -FLT_MAX;
            #pragma unroll
            for (int t = 0; t < 16; t++) if (t < nt) {
                float p = pr[t];
                if (p < cur && p > lm) lm = p;
            }
            for (int o = 16; o; o >>= 1) lm = fmaxf(lm, __shfl_xor_sync(~0u, lm, o));
            int lc = 0;
            #pragma unroll
            for (int t = 0; t < 16; t++) if (t < nt) if (pr[t] == lm) lc++;
            for (int o = 16; o; o >>= 1) lc += __shfl_xor_sync(~0u, lc, o);
            if (it == 0) m1 = lm;
            kept += lc;
            cur = lm;
        }
        float thresh = cur;
        float sum2 = 0.f;
        #pragma unroll
        for (int t = 0; t < 16; t++) if (t < nt) {
            float p = pr[t];
            float wt = (p >= thresh) ? expf(p - m1) : 0.f;
            pr[t] = wt; sum2 += wt;
        }
        for (int o = 16; o; o >>= 1) sum2 += __shfl_xor_sync(~0u, sum2, o);
        float inv2 = 1.f / sum2;
        #pragma unroll
        for (int t = 0; t < 16; t++) if (t < nt) pr[t] *= inv2;
    }
}

__global__ __launch_bounds__(256, 2)
void attn_kernel(const float* __restrict__ qk, const float* __restrict__ v,
                 float* __restrict__ out) {
    extern __shared__ __align__(16) char sm[];
    __half2* tb = (__half2*)sm;                        // K/V tile union
    float*   sc = (float*)(sm + AOFF_SC);              // [16][34]
    __half*  pH = (__half*)(sm + AOFF_PH);             // [16][520]
    __half*  pL = (__half*)(sm + AOFF_PL);             // [16][520]

    int tid = threadIdx.x, lane = tid & 31, wid = tid >> 5;
    int qa = lane & 3, g = lane >> 2;
    int blk = blockIdx.x;
    int bh = blk >> 5, i0 = (blk & 31) * 16;           // 32 blocks per (b,h)
    int b = bh >> 3, h = bh & 7;
    int ntiles = (i0 + 15 + 31) >> 5;                  // keys needed: < i0+15

    // ---- Q fragments (warps 0-3: rows g and g+8) + prefill K tile 0 (warps 4-7) ----
    unsigned qfh[4][4], qfl[4][4];
    if (wid < 4) {
        size_t q0 = ((size_t)(b * S_ + i0 + g))     * D_ + h * DH_;
        size_t q8 = ((size_t)(b * S_ + i0 + g + 8)) * D_ + h * DH_;
        #pragma unroll
        for (int s = 0; s < 4; s++) {
            __half2 hh, ll;
            float2 f;
            f = *(const float2*)&qk[q0 + s * 16 + 2 * qa];
            split2(f.x, f.y, hh, ll); qfh[s][0] = *(unsigned*)&hh; qfl[s][0] = *(unsigned*)&ll;
            f = *(const float2*)&qk[q8 + s * 16 + 2 * qa];
            split2(f.x, f.y, hh, ll); qfh[s][1] = *(unsigned*)&hh; qfl[s][1] = *(unsigned*)&ll;
            f = *(const float2*)&qk[q0 + s * 16 + 2 * qa + 8];
            split2(f.x, f.y, hh, ll); qfh[s][2] = *(unsigned*)&hh; qfl[s][2] = *(unsigned*)&ll;
            f = *(const float2*)&qk[q8 + s * 16 + 2 * qa + 8];
            split2(f.x, f.y, hh, ll); qfh[s][3] = *(unsigned*)&hh; qfl[s][3] = *(unsigned*)&ll;
        }
    } else {
        fillK(tb, tb + 1280, qk, b, h, 0, tid);
    }
    __syncthreads();

    // ---- phase 1: QK scores -> registers (warp w owns rows w, w+8) ----
    float pr0[16], pr1[16];
    int iq0 = i0 + wid;        // query index of row wid
    int iq1 = i0 + wid + 8;    // query index of row wid+8

    for (int t = 0; t < ntiles; t++) {
        if (wid < 4) {
            __half2* Kh = tb + (t & 1) * 2560;
            __half2* Kl = Kh + 1280;
            int n = wid * 8 + g;
            float c[4] = {0.f, 0.f, 0.f, 0.f};
            #pragma unroll
            for (int s = 0; s < 4; s++) {
                unsigned Bhf[2], Blf[2];
                Bhf[0] = *(const unsigned*)&Kh[(s * 8 + qa)     * KST + n];
                Bhf[1] = *(const unsigned*)&Kh[(s * 8 + qa + 4) * KST + n];
                Blf[0] = *(const unsigned*)&Kl[(s * 8 + qa)     * KST + n];
                Blf[1] = *(const unsigned*)&Kl[(s * 8 + qa + 4) * KST + n];
                mma_f16(c, qfl[s], Bhf);
                mma_f16(c, qfh[s], Blf);
                mma_f16(c, qfh[s], Bhf);
            }
            *(float2*)&sc[g * 34 + wid * 8 + 2 * qa]       = make_float2(c[0], c[1]);
            *(float2*)&sc[(g + 8) * 34 + wid * 8 + 2 * qa] = make_float2(c[2], c[3]);
        } else if (t + 1 < ntiles) {
            __half2* Kh = tb + ((t + 1) & 1) * 2560;
            fillK(Kh, Kh + 1280, qk, b, h, (t + 1) * 32, tid);
        }
        __syncthreads();
        int j = t * 32 + lane;
        float r0 = sc[wid * 34 + lane];
        float r1 = sc[(wid + 8) * 34 + lane];
        pr0[t] = (j < iq0) ? r0 * 0.125f : -1e30f;
        pr1[t] = (j < iq1) ? r1 * 0.125f : -1e30f;
        __syncthreads();
    }

    // ---- phase 2+3: register softmax + top-k ----
    reg_softmax(pr0, ntiles, iq0, lane);
    reg_softmax(pr1, ntiles, iq1, lane);

    // ---- write probs as hi/lo fp16 (row 0 of batch zeroed: zero_pad) ----
    #pragma unroll
    for (int t = 0; t < 16; t++) if (t < ntiles) {
        int j = t * 32 + lane;
        float p0 = (iq0 == 0) ? 0.f : pr0[t];
        float p1 = pr1[t];                      // iq1 >= 8, never row 0
        __half hp0 = __float2half_rn(p0);
        __half hp1 = __float2half_rn(p1);
        pH[wid * PBH + j]       = hp0;
        pL[wid * PBH + j]       = __float2half_rn(p0 - __half2float(hp0));
        pH[(wid + 8) * PBH + j] = hp1;
        pL[(wid + 8) * PBH + j] = __float2half_rn(p1 - __half2float(hp1));
    }
    fillV(tb, tb + 1168, v, b, h, 0, tid);
    __syncthreads();

    // ---- phase 4: PV via MMA; warp w owns d-tile w; all 16 rows active ----
    float c[4] = {0.f, 0.f, 0.f, 0.f};
    for (int t = 0; t < ntiles; t++) {
        __half2* Vh = tb + (t & 1) * 2336;
        __half2* Vl = Vh + 1168;
        int n = wid * 8 + g;
        #pragma unroll
        for (int s = 0; s < 2; s++) {
            int jb = t * 32 + s * 16;
            unsigned Af_h[4], Af_l[4];
            Af_h[0] = *(const unsigned*)&pH[g * PBH + jb + 2 * qa];
            Af_h[1] = *(const unsigned*)&pH[(g + 8) * PBH + jb + 2 * qa];
            Af_h[2] = *(const unsigned*)&pH[g * PBH + jb + 2 * qa + 8];
            Af_h[3] = *(const unsigned*)&pH[(g + 8) * PBH + jb + 2 * qa + 8];
            Af_l[0] = *(const unsigned*)&pL[g * PBH + jb + 2 * qa];
            Af_l[1] = *(const unsigned*)&pL[(g + 8) * PBH + jb + 2 * qa];
            Af_l[2] = *(const unsigned*)&pL[g * PBH + jb + 2 * qa + 8];
            Af_l[3] = *(const unsigned*)&pL[(g + 8) * PBH + jb + 2 * qa + 8];
            unsigned Bhf[2], Blf[2];
            Bhf[0] = *(const unsigned*)&Vh[(s * 8 + qa)     * VST + n];
            Bhf[1] = *(const unsigned*)&Vh[(s * 8 + qa + 4) * VST + n];
            Blf[0] = *(const unsigned*)&Vl[(s * 8 + qa)     * VST + n];
            Blf[1] = *(const unsigned*)&Vl[(s * 8 + qa + 4) * VST + n];
            mma_f16(c, Af_l, Bhf);
            mma_f16(c, Af_h, Blf);
            mma_f16(c, Af_h, Bhf);
        }
        if (t + 1 < ntiles) {
            __half2* nVh = tb + ((t + 1) & 1) * 2336;
            fillV(nVh, nVh + 1168, v, b, h, (t + 1) * 32, tid);
        }
        __syncthreads();
    }

    // ---- epilogue: rows g (c0,c1) and g+8 (c2,c3) ----
    size_t o0 = ((size_t)(b * S_ + i0 + g))     * D_ + h * DH_ + wid * 8 + 2 * qa;
    size_t o8 = ((size_t)(b * S_ + i0 + g + 8)) * D_ + h * DH_ + wid * 8 + 2 * qa;
    *(float2*)&out[o0] = make_float2(c[0], c[1]);
    *(float2*)&out[o8] = make_float2(c[2], c[3]);
}

// ---------------- out = LayerNorm(xin + delta) * g + b (float4) ----------------
__global__ __launch_bounds__(128)
void resid_ln_kernel(const float* __restrict__ xin, const float* __restrict__ delta,
                     const float* __restrict__ g, const float* __restrict__ bta,
                     float* __restrict__ out) {
    __shared__ float red[4];
    int row = blockIdx.x;
    int t = threadIdx.x;            // 128 threads x float4
    float4 xv = *(const float4*)&xin[(size_t)row * D_ + 4 * t];
    float4 dv = *(const float4*)&delta[(size_t)row * D_ + 4 * t];
    float v[4] = {xv.x + dv.x, xv.y + dv.y, xv.z + dv.z, xv.w + dv.w};
    float s = v[0] + v[1] + v[2] + v[3];
    for (int o = 16; o; o >>= 1) s += __shfl_xor_sync(~0u, s, o);
    if ((t & 31) == 0) red[t >> 5] = s;
    __syncthreads();
    s = red[0] + red[1] + red[2] + red[3];
    float mean = s * (1.f / D_);

    float sq = 0.f;
    #pragma unroll
    for (int e = 0; e < 4; e++) { float dd = v[e] - mean; sq += dd * dd; }
    __syncthreads();
    for (int o = 16; o; o >>= 1) sq += __shfl_xor_sync(~0u, sq, o);
    if ((t & 31) == 0) red[t >> 5] = sq;
    __syncthreads();
    sq = red[0] + red[1] + red[2] + red[3];
    float rstd = rsqrtf(sq * (1.f / D_) + 1e-5f);

    float4 gv = *(const float4*)&g[4 * t];
    float4 bv = *(const float4*)&bta[4 * t];
    float4 o4;
    o4.x = (v[0] - mean) * rstd * gv.x + bv.x;
    o4.y = (v[1] - mean) * rstd * gv.y + bv.y;
    o4.z = (v[2] - mean) * rstd * gv.z + bv.z;
    o4.w = (v[3] - mean) * rstd * gv.w + bv.w;
    *(float4*)&out[(size_t)row * D_ + 4 * t] = o4;
}

// ---------------- launcher ----------------
extern "C" void kernel_launch(void* const* d_in, const int* in_sizes, int n_in,
                              void* d_out, int out_size) {
    const float* question = (const float*)d_in[0];
    const float* inter    = (const float*)d_in[1];
    const float* pos      = (const float*)d_in[2];
    const float* Wk  = (const float*)d_in[3];
    const float* bk  = (const float*)d_in[4];
    const float* Wv  = (const float*)d_in[5];
    const float* bv  = (const float*)d_in[6];
    const float* Wo  = (const float*)d_in[7];
    const float* bo  = (const float*)d_in[8];
    const float* ln1g = (const float*)d_in[9];
    const float* ln1b = (const float*)d_in[10];
    const float* W1  = (const float*)d_in[11];
    const float* b1  = (const float*)d_in[12];
    const float* W2  = (const float*)d_in[13];
    const float* b2  = (const float*)d_in[14];
    const float* ln2g = (const float*)d_in[15];
    const float* ln2b = (const float*)d_in[16];

    float *x, *y, *qkb, *vb, *attnb, *tmpb, *ffb;
    cudaGetSymbolAddress((void**)&x,     g_x);
    cudaGetSymbolAddress((void**)&y,     g_y);
    cudaGetSymbolAddress((void**)&qkb,   g_qk);
    cudaGetSymbolAddress((void**)&vb,    g_v);
    cudaGetSymbolAddress((void**)&attnb, g_attn);
    cudaGetSymbolAddress((void**)&tmpb,  g_tmp);
    cudaGetSymbolAddress((void**)&ffb,   g_ff);

    cudaFuncSetAttribute(gemm_f16x3, cudaFuncAttributeMaxDynamicSharedMemorySize,
                         GSMEM_BYTES);
    cudaFuncSetAttribute(attn_kernel, cudaFuncAttributeMaxDynamicSharedMemorySize,
                         ASMEM_BYTES);

    add_pos_kernel<<<(B_ * S_ * D_) / 256, 256>>>(question, inter, pos);

    for (int l = 0; l < L_; l++) {
        const float* Wkl = Wk + (size_t)l * D_ * D_;
        const float* Wvl = Wv + (size_t)l * D_ * D_;
        const float* Wol = Wo + (size_t)l * D_ * D_;
        const float* W1l = W1 + (size_t)l * D_ * DFF_;
        const float* W2l = W2 + (size_t)l * DFF_ * D_;

        dim3 gD(D_ / 128, M_ / 128);       // 4 x 128
        dim3 gF(DFF_ / 128, M_ / 128);     // 16 x 128

        gemm_f16x3<<<gD, 256, GSMEM_BYTES>>>(x, Wkl, bk + l * D_, qkb, D_, D_, 0);
        gemm_f16x3<<<gD, 256, GSMEM_BYTES>>>(y, Wvl, bv + l * D_, vb,  D_, D_, 0);
        attn_kernel<<<B_ * H_ * (S_ / 16), 256, ASMEM_BYTES>>>(qkb, vb, attnb);
        gemm_f16x3<<<gD, 256, GSMEM_BYTES>>>(attnb, Wol, bo + l * D_, tmpb, D_, D_, 0);
        resid_ln_kernel<<<M_, 128>>>(x, tmpb, ln1g + l * D_, ln1b + l * D_, x);
        gemm_f16x3<<<gF, 256, GSMEM_BYTES>>>(x, W1l, b1 + l * DFF_, ffb, D_, DFF_, 1);
        gemm_f16x3<<<gD, 256, GSMEM_BYTES>>>(ffb, W2l, b2 + l * D_, tmpb, DFF_, D_, 0);
        float* lnout = (l == L_ - 1) ? (float*)d_out : x;
        resid_ln_kernel<<<M_, 128>>>(x, tmpb, ln2g + l * D_, ln2b + l * D_, lnout);
    }
}